// round 1
// baseline (speedup 1.0000x reference)
#include <cuda_runtime.h>
#include <cstdint>

#define BATCHN 4
#define SEQL   2048
#define EMB    1024
#define NHEAD  16
#define DKH    64
#define MROWS  (BATCHN*SEQL)   /* 8192 */

// ---------------- scratch (static device globals; no runtime allocation) ----
__device__ float g_q[(size_t)BATCHN*NHEAD*SEQL*DKH];     // [b,h,s,d]
__device__ float g_k[(size_t)BATCHN*NHEAD*SEQL*DKH];
__device__ float g_v[(size_t)BATCHN*NHEAD*SEQL*DKH];
__device__ float g_attn[(size_t)MROWS*EMB];              // [b,s,h*d]

// ---------------- helpers ---------------------------------------------------
__device__ __forceinline__ unsigned f2tf(float x) {
    unsigned r;
    asm("cvt.rna.tf32.f32 %0, %1;" : "=r"(r) : "f"(x));
    return r;
}
__device__ __forceinline__ void split_tf32(float x, unsigned &hi, unsigned &lo) {
    hi = f2tf(x);
    lo = f2tf(x - __uint_as_float(hi));
}
__device__ __forceinline__ void mma8(float c[4], const unsigned a[4], const unsigned b[2]) {
    asm volatile(
        "mma.sync.aligned.m16n8k8.row.col.f32.tf32.tf32.f32 "
        "{%0,%1,%2,%3},{%4,%5,%6,%7},{%8,%9},{%0,%1,%2,%3};\n"
        : "+f"(c[0]), "+f"(c[1]), "+f"(c[2]), "+f"(c[3])
        : "r"(a[0]), "r"(a[1]), "r"(a[2]), "r"(a[3]), "r"(b[0]), "r"(b[1]));
}

// ---------------- GEMM (TF32x3): C = A(MxK) * B(KxN) ------------------------
// mode 0: per-head projection. B = Bw + head*K*64 (head = blockIdx.y, ldb=64),
//         C = g_q/g_k/g_v (sel), layout [b,h,s,d].
// mode 1: output projection.  A = g_attn, B = w_o (ldb=1024, col off = by*64),
//         C = Cext row-major [8192,1024].
__global__ void __launch_bounds__(256) gemm_x3_kernel(
    const float* __restrict__ Ain, const float* __restrict__ Bw,
    float* __restrict__ Cext, int Kdim, int mode, int sel)
{
    __shared__ float As[128 * 36];   // 128 x (32+4)
    __shared__ float Bs[32 * 68];    // 32  x (64+4)

    const int tid  = threadIdx.x;
    const int lane = tid & 31;
    const int warp = tid >> 5;
    const int wm = warp >> 1;        // 0..3
    const int wn = warp & 1;         // 0..1
    const int row0 = blockIdx.x * 128;

    const float* A = Ain;
    const float* Bt;
    int ldb, n0;
    if (mode == 0) { Bt = Bw + (size_t)blockIdx.y * Kdim * 64; ldb = 64;  n0 = 0; }
    else           { A = g_attn; Bt = Bw; ldb = EMB; n0 = blockIdx.y * 64; }

    float acc[2][4][4];
#pragma unroll
    for (int i = 0; i < 2; i++)
#pragma unroll
        for (int j = 0; j < 4; j++)
#pragma unroll
            for (int r = 0; r < 4; r++) acc[i][j][r] = 0.f;

    for (int k0 = 0; k0 < Kdim; k0 += 32) {
        // load A tile 128x32 (float4, coalesced)
#pragma unroll
        for (int ii = 0; ii < 4; ii++) {
            int i = tid + ii * 256;
            int r = i >> 3, c4 = (i & 7) << 2;
            float4 a4 = *reinterpret_cast<const float4*>(A + (size_t)(row0 + r) * Kdim + k0 + c4);
            float* d = As + r * 36 + c4;
            d[0] = a4.x; d[1] = a4.y; d[2] = a4.z; d[3] = a4.w;
        }
        // load B tile 32x64
#pragma unroll
        for (int ii = 0; ii < 2; ii++) {
            int i = tid + ii * 256;
            int r = i >> 4, c4 = (i & 15) << 2;
            float4 b4 = *reinterpret_cast<const float4*>(Bt + (size_t)(k0 + r) * ldb + n0 + c4);
            float* d = Bs + r * 68 + c4;
            d[0] = b4.x; d[1] = b4.y; d[2] = b4.z; d[3] = b4.w;
        }
        __syncthreads();

#pragma unroll
        for (int ks = 0; ks < 4; ks++) {
            const int kk = ks * 8;
            unsigned ah[2][4], al[2][4];
#pragma unroll
            for (int mt = 0; mt < 2; mt++) {
                int rb = wm * 32 + mt * 16 + (lane >> 2);
                split_tf32(As[rb * 36 + kk + (lane & 3)],           ah[mt][0], al[mt][0]);
                split_tf32(As[(rb + 8) * 36 + kk + (lane & 3)],     ah[mt][1], al[mt][1]);
                split_tf32(As[rb * 36 + kk + 4 + (lane & 3)],       ah[mt][2], al[mt][2]);
                split_tf32(As[(rb + 8) * 36 + kk + 4 + (lane & 3)], ah[mt][3], al[mt][3]);
            }
            unsigned bh2[4][2], bl2[4][2];
#pragma unroll
            for (int nt = 0; nt < 4; nt++) {
                int nb = wn * 32 + nt * 8 + (lane >> 2);
                split_tf32(Bs[(kk + (lane & 3)) * 68 + nb],     bh2[nt][0], bl2[nt][0]);
                split_tf32(Bs[(kk + 4 + (lane & 3)) * 68 + nb], bh2[nt][1], bl2[nt][1]);
            }
#pragma unroll
            for (int mt = 0; mt < 2; mt++)
#pragma unroll
                for (int nt = 0; nt < 4; nt++) {
                    mma8(acc[mt][nt], ah[mt], bh2[nt]);   // hi*hi
                    mma8(acc[mt][nt], ah[mt], bl2[nt]);   // hi*lo
                    mma8(acc[mt][nt], al[mt], bh2[nt]);   // lo*hi
                }
        }
        __syncthreads();
    }

    float* Cq = (mode == 0) ? (sel == 0 ? g_q : (sel == 1 ? g_k : g_v)) : Cext;
#pragma unroll
    for (int mt = 0; mt < 2; mt++) {
        int r = row0 + wm * 32 + mt * 16 + (lane >> 2);
#pragma unroll
        for (int nt = 0; nt < 4; nt++) {
            int c = wn * 32 + nt * 8 + (lane & 3) * 2;
            if (mode == 0) {
                int b = r >> 11, s = r & 2047;
                size_t base  = (((size_t)b * NHEAD + blockIdx.y) * SEQL + s) * DKH;
                size_t base2 = base + (size_t)8 * DKH;   // row+8 stays in same batch
                Cq[base + c]      = acc[mt][nt][0];
                Cq[base + c + 1]  = acc[mt][nt][1];
                Cq[base2 + c]     = acc[mt][nt][2];
                Cq[base2 + c + 1] = acc[mt][nt][3];
            } else {
                size_t base = (size_t)r * EMB + blockIdx.y * 64 + c;
                Cq[base]            = acc[mt][nt][0];
                Cq[base + 1]        = acc[mt][nt][1];
                Cq[base + 8 * EMB]      = acc[mt][nt][2];
                Cq[base + 8 * EMB + 1]  = acc[mt][nt][3];
            }
        }
    }
}

// ---------------- flash attention (causal), TF32x3 for S, V split for PV ----
// grid: (SEQL/64, BATCHN*NHEAD); block 128 (4 warps, 16 q-rows each)
#define FLD 68
#define FSM_BYTES (3 * 64 * FLD * 4)

__global__ void __launch_bounds__(128) flash_kernel(const int* __restrict__ maskp)
{
    extern __shared__ float sm[];
    float* Ks  = sm;                  // [64][68]  K tile (row = kv pos, col = d)
    float* Vts = sm + 64 * FLD;       // [64][68]  V^T tile (row = d, col = kv)
    float* Ps  = sm + 2 * 64 * FLD;   // [64][68]  P tile (also Q staging)

    const int tid  = threadIdx.x;
    const int lane = tid & 31;
    const int warp = tid >> 5;
    const int qt = blockIdx.x;
    const int bh = blockIdx.y;
    const int b = bh >> 4, h = bh & 15;
    const int q0 = qt * 64;

    const float* Q = g_q + (size_t)bh * SEQL * DKH;
    const float* K = g_k + (size_t)bh * SEQL * DKH;
    const float* V = g_v + (size_t)bh * SEQL * DKH;

    // ---- stage Q tile (scaled by 8 = 1/sqrt(1/dk)) into Ps, then to regs ----
#pragma unroll
    for (int ii = 0; ii < 8; ii++) {
        int i = tid + ii * 128;
        int r = i >> 4, c4 = (i & 15) << 2;
        float4 v4 = *reinterpret_cast<const float4*>(Q + (size_t)(q0 + r) * DKH + c4);
        float* d = Ps + r * FLD + c4;
        d[0] = v4.x * 8.f; d[1] = v4.y * 8.f; d[2] = v4.z * 8.f; d[3] = v4.w * 8.f;
    }
    __syncthreads();

    const int rl = warp * 16 + (lane >> 2);   // local row (first of the two)
    const int kq = lane & 3;
    unsigned qhi[8][4], qlo[8][4];
#pragma unroll
    for (int ks = 0; ks < 8; ks++) {
        split_tf32(Ps[rl * FLD + ks * 8 + kq],           qhi[ks][0], qlo[ks][0]);
        split_tf32(Ps[(rl + 8) * FLD + ks * 8 + kq],     qhi[ks][1], qlo[ks][1]);
        split_tf32(Ps[rl * FLD + ks * 8 + 4 + kq],       qhi[ks][2], qlo[ks][2]);
        split_tf32(Ps[(rl + 8) * FLD + ks * 8 + 4 + kq], qhi[ks][3], qlo[ks][3]);
    }

    float m[2] = { -1e30f, -1e30f };
    float l[2] = { 0.f, 0.f };
    float o[8][4];
#pragma unroll
    for (int i = 0; i < 8; i++)
#pragma unroll
        for (int j = 0; j < 4; j++) o[i][j] = 0.f;

    const int maskv = maskp[0];               // nonzero bits => causal (robust to int/float encodings)
    const int ntiles = maskv ? (qt + 1) : (SEQL / 64);

    for (int t = 0; t < ntiles; t++) {
        const int kv0 = t * 64;
        // ---- cooperative K / V^T tile load ----
#pragma unroll
        for (int ii = 0; ii < 8; ii++) {
            int i = tid + ii * 128;
            int r = i >> 4, c4 = (i & 15) << 2;
            float4 k4 = *reinterpret_cast<const float4*>(K + (size_t)(kv0 + r) * DKH + c4);
            float* dk = Ks + r * FLD + c4;
            dk[0] = k4.x; dk[1] = k4.y; dk[2] = k4.z; dk[3] = k4.w;
            float4 v4 = *reinterpret_cast<const float4*>(V + (size_t)(kv0 + r) * DKH + c4);
            Vts[(c4 + 0) * FLD + r] = v4.x;
            Vts[(c4 + 1) * FLD + r] = v4.y;
            Vts[(c4 + 2) * FLD + r] = v4.z;
            Vts[(c4 + 3) * FLD + r] = v4.w;
        }
        __syncthreads();

        // ---- S = Q K^T (TF32x3), already scaled by 8 via Q ----
        float s[8][4];
#pragma unroll
        for (int i = 0; i < 8; i++)
#pragma unroll
            for (int j = 0; j < 4; j++) s[i][j] = 0.f;

#pragma unroll
        for (int ks = 0; ks < 8; ks++) {
            const int kk = ks * 8;
#pragma unroll
            for (int nt = 0; nt < 8; nt++) {
                int nb = nt * 8 + (lane >> 2);
                unsigned b0h, b0l, b1h, b1l;
                split_tf32(Ks[nb * FLD + kk + (lane & 3)],     b0h, b0l);
                split_tf32(Ks[nb * FLD + kk + 4 + (lane & 3)], b1h, b1l);
                unsigned bhv[2] = { b0h, b1h };
                unsigned blv[2] = { b0l, b1l };
                mma8(s[nt], qhi[ks], bhv);
                mma8(s[nt], qhi[ks], blv);
                mma8(s[nt], qlo[ks], bhv);
            }
        }

        // ---- causal mask on diagonal tile ----
        if (maskv && t == qt) {
            int rg0 = q0 + rl;
#pragma unroll
            for (int nt = 0; nt < 8; nt++) {
                int cg = kv0 + nt * 8 + (lane & 3) * 2;
                if (cg > rg0)         s[nt][0] = -1e30f;
                if (cg + 1 > rg0)     s[nt][1] = -1e30f;
                if (cg > rg0 + 8)     s[nt][2] = -1e30f;
                if (cg + 1 > rg0 + 8) s[nt][3] = -1e30f;
            }
        }

        // ---- online softmax ----
#pragma unroll
        for (int sub = 0; sub < 2; sub++) {
            float tm = -1e30f;
#pragma unroll
            for (int nt = 0; nt < 8; nt++)
                tm = fmaxf(tm, fmaxf(s[nt][2 * sub], s[nt][2 * sub + 1]));
            tm = fmaxf(tm, __shfl_xor_sync(0xffffffffu, tm, 1));
            tm = fmaxf(tm, __shfl_xor_sync(0xffffffffu, tm, 2));
            float mn = fmaxf(m[sub], tm);
            float alpha = __expf(m[sub] - mn);
            float rs = 0.f;
#pragma unroll
            for (int nt = 0; nt < 8; nt++) {
                float p0 = __expf(s[nt][2 * sub] - mn);
                float p1 = __expf(s[nt][2 * sub + 1] - mn);
                s[nt][2 * sub] = p0; s[nt][2 * sub + 1] = p1;
                rs += p0 + p1;
            }
            rs += __shfl_xor_sync(0xffffffffu, rs, 1);
            rs += __shfl_xor_sync(0xffffffffu, rs, 2);
            l[sub] = l[sub] * alpha + rs;
            m[sub] = mn;
#pragma unroll
            for (int dt = 0; dt < 8; dt++) {
                o[dt][2 * sub]     *= alpha;
                o[dt][2 * sub + 1] *= alpha;
            }
        }

        // ---- store P (tf32-rounded) to SMEM for the PV MMA ----
#pragma unroll
        for (int nt = 0; nt < 8; nt++) {
            int c = nt * 8 + (lane & 3) * 2;
            Ps[rl * FLD + c]           = __uint_as_float(f2tf(s[nt][0]));
            Ps[rl * FLD + c + 1]       = __uint_as_float(f2tf(s[nt][1]));
            Ps[(rl + 8) * FLD + c]     = __uint_as_float(f2tf(s[nt][2]));
            Ps[(rl + 8) * FLD + c + 1] = __uint_as_float(f2tf(s[nt][3]));
        }
        __syncthreads();

        // ---- O += P * V  (P single tf32, V split hi/lo 2-pass) ----
#pragma unroll
        for (int ks = 0; ks < 8; ks++) {
            int kkk = ks * 8 + (lane & 3);
            unsigned pa[4];
            pa[0] = __float_as_uint(Ps[rl * FLD + kkk]);
            pa[1] = __float_as_uint(Ps[(rl + 8) * FLD + kkk]);
            pa[2] = __float_as_uint(Ps[rl * FLD + kkk + 4]);
            pa[3] = __float_as_uint(Ps[(rl + 8) * FLD + kkk + 4]);
#pragma unroll
            for (int dt = 0; dt < 8; dt++) {
                int db = dt * 8 + (lane >> 2);
                unsigned b0h, b0l, b1h, b1l;
                split_tf32(Vts[db * FLD + ks * 8 + (lane & 3)],     b0h, b0l);
                split_tf32(Vts[db * FLD + ks * 8 + 4 + (lane & 3)], b1h, b1l);
                unsigned bhv[2] = { b0h, b1h };
                unsigned blv[2] = { b0l, b1l };
                mma8(o[dt], pa, bhv);
                mma8(o[dt], pa, blv);
            }
        }
        __syncthreads();
    }

    // ---- epilogue: write attn[b, q, h, d] = O / l ----
    float i0 = 1.f / l[0];
    float i1 = 1.f / l[1];
    int rg = q0 + rl;
    size_t ob  = (((size_t)b * SEQL + rg) * NHEAD + h) * DKH;
    size_t ob2 = (((size_t)b * SEQL + rg + 8) * NHEAD + h) * DKH;
#pragma unroll
    for (int dt = 0; dt < 8; dt++) {
        int c = dt * 8 + (lane & 3) * 2;
        g_attn[ob + c]      = o[dt][0] * i0;
        g_attn[ob + c + 1]  = o[dt][1] * i0;
        g_attn[ob2 + c]     = o[dt][2] * i1;
        g_attn[ob2 + c + 1] = o[dt][3] * i1;
    }
}

// ---------------- launcher ---------------------------------------------------
extern "C" void kernel_launch(void* const* d_in, const int* in_sizes, int n_in,
                              void* d_out, int out_size)
{
    const float* x_q = (const float*)d_in[0];
    const float* x_k = (const float*)d_in[1];
    const float* x_v = (const float*)d_in[2];
    const float* w_q = (const float*)d_in[3];
    const float* w_k = (const float*)d_in[4];
    const float* w_v = (const float*)d_in[5];
    const float* w_o = (const float*)d_in[6];
    const int*   msk = (const int*)d_in[7];
    float* out = (float*)d_out;

    cudaFuncSetAttribute(flash_kernel, cudaFuncAttributeMaxDynamicSharedMemorySize, FSM_BYTES);

    dim3 gproj(MROWS / 128, NHEAD);
    gemm_x3_kernel<<<gproj, 256>>>(x_q, w_q, nullptr, EMB, 0, 0);
    gemm_x3_kernel<<<gproj, 256>>>(x_k, w_k, nullptr, EMB, 0, 1);
    gemm_x3_kernel<<<gproj, 256>>>(x_v, w_v, nullptr, EMB, 0, 2);

    flash_kernel<<<dim3(SEQL / 64, BATCHN * NHEAD), 128, FSM_BYTES>>>(msk);

    gemm_x3_kernel<<<dim3(MROWS / 128, EMB / 64), 256>>>(nullptr, w_o, out, EMB, 1, 0);
}

// round 2
// speedup vs baseline: 1.2628x; 1.2628x over previous
#include <cuda_runtime.h>
#include <cstdint>

#define BATCHN 4
#define SEQL   2048
#define EMB    1024
#define NHEAD  16
#define DKH    64
#define MROWS  (BATCHN*SEQL)   /* 8192 */

// ---------------- scratch (static device globals; no runtime allocation) ----
__device__ float g_q[(size_t)BATCHN*NHEAD*SEQL*DKH];     // [b,h,s,d]
__device__ float g_k[(size_t)BATCHN*NHEAD*SEQL*DKH];
__device__ float g_v[(size_t)BATCHN*NHEAD*SEQL*DKH];
__device__ float g_attn[(size_t)MROWS*EMB];              // [b,s,h*d]

// ---------------- helpers ---------------------------------------------------
__device__ __forceinline__ unsigned f2tf(float x) {
    unsigned r;
    asm("cvt.rna.tf32.f32 %0, %1;" : "=r"(r) : "f"(x));
    return r;
}
__device__ __forceinline__ void split_tf32(float x, unsigned &hi, unsigned &lo) {
    hi = f2tf(x);
    lo = f2tf(x - __uint_as_float(hi));
}
__device__ __forceinline__ void mma8(float c[4], const unsigned a[4], const unsigned b[2]) {
    asm volatile(
        "mma.sync.aligned.m16n8k8.row.col.f32.tf32.tf32.f32 "
        "{%0,%1,%2,%3},{%4,%5,%6,%7},{%8,%9},{%0,%1,%2,%3};\n"
        : "+f"(c[0]), "+f"(c[1]), "+f"(c[2]), "+f"(c[3])
        : "r"(a[0]), "r"(a[1]), "r"(a[2]), "r"(a[3]), "r"(b[0]), "r"(b[1]));
}

// ---------------- GEMM (TF32x3), pre-split SMEM tiles, reg double-buffer ----
// MODE 0: per-head projections. z = 0/1/2 -> q/k/v. B = W + head*1024*64.
// MODE 1: output projection. A = g_attn, B = w_o, C = Cext.
#define GA_LD 36
#define GB_LD 72
#define GSM_FLOATS (2*128*GA_LD + 2*32*GB_LD)
#define GSM_BYTES  (GSM_FLOATS*4)

template<int MODE>
__global__ void __launch_bounds__(256) gemm_x3_kernel(
    const float* __restrict__ A0, const float* __restrict__ A1, const float* __restrict__ A2,
    const float* __restrict__ B0, const float* __restrict__ B1, const float* __restrict__ B2,
    float* __restrict__ Cext)
{
    extern __shared__ float sm[];
    float* Ah = sm;
    float* Al = Ah + 128 * GA_LD;
    float* Bh = Al + 128 * GA_LD;
    float* Bl = Bh + 32 * GB_LD;

    const int tid  = threadIdx.x;
    const int lane = tid & 31;
    const int warp = tid >> 5;
    const int wm = warp >> 1, wn = warp & 1;
    const int r8 = lane >> 2, lq = lane & 3;
    const int row0 = blockIdx.x * 128;

    const float* A;
    const float* Bt;
    int ldb, n0;
    float* Cq;
    if (MODE == 0) {
        int sel = blockIdx.z;
        A = sel == 0 ? A0 : (sel == 1 ? A1 : A2);
        const float* W = sel == 0 ? B0 : (sel == 1 ? B1 : B2);
        Bt = W + (size_t)blockIdx.y * EMB * 64; ldb = 64; n0 = 0;
        Cq = sel == 0 ? g_q : (sel == 1 ? g_k : g_v);
    } else {
        A = g_attn; Bt = B0; ldb = EMB; n0 = blockIdx.y * 64; Cq = Cext;
    }

    float acc[2][4][4];
#pragma unroll
    for (int i = 0; i < 2; i++)
#pragma unroll
        for (int j = 0; j < 4; j++)
#pragma unroll
            for (int r = 0; r < 4; r++) acc[i][j][r] = 0.f;

    float4 ra[4], rbuf[2];

    // prologue load (k0 = 0)
#pragma unroll
    for (int ii = 0; ii < 4; ii++) {
        int i = tid + ii * 256; int r = i >> 3, c4 = (i & 7) << 2;
        ra[ii] = *reinterpret_cast<const float4*>(A + (size_t)(row0 + r) * EMB + c4);
    }
#pragma unroll
    for (int ii = 0; ii < 2; ii++) {
        int i = tid + ii * 256; int r = i >> 4, c4 = (i & 15) << 2;
        rbuf[ii] = *reinterpret_cast<const float4*>(Bt + (size_t)r * ldb + n0 + c4);
    }

    for (int k0 = 0; k0 < EMB; k0 += 32) {
        // ---- split + store current tile ----
#pragma unroll
        for (int ii = 0; ii < 4; ii++) {
            int i = tid + ii * 256; int r = i >> 3, c4 = (i & 7) << 2;
            float v[4] = { ra[ii].x, ra[ii].y, ra[ii].z, ra[ii].w };
#pragma unroll
            for (int j = 0; j < 4; j++) {
                unsigned h, l; split_tf32(v[j], h, l);
                Ah[r * GA_LD + c4 + j] = __uint_as_float(h);
                Al[r * GA_LD + c4 + j] = __uint_as_float(l);
            }
        }
#pragma unroll
        for (int ii = 0; ii < 2; ii++) {
            int i = tid + ii * 256; int r = i >> 4, c4 = (i & 15) << 2;
            float v[4] = { rbuf[ii].x, rbuf[ii].y, rbuf[ii].z, rbuf[ii].w };
#pragma unroll
            for (int j = 0; j < 4; j++) {
                unsigned h, l; split_tf32(v[j], h, l);
                Bh[r * GB_LD + c4 + j] = __uint_as_float(h);
                Bl[r * GB_LD + c4 + j] = __uint_as_float(l);
            }
        }
        __syncthreads();

        // ---- prefetch next tile into regs ----
        if (k0 + 32 < EMB) {
#pragma unroll
            for (int ii = 0; ii < 4; ii++) {
                int i = tid + ii * 256; int r = i >> 3, c4 = (i & 7) << 2;
                ra[ii] = *reinterpret_cast<const float4*>(A + (size_t)(row0 + r) * EMB + k0 + 32 + c4);
            }
#pragma unroll
            for (int ii = 0; ii < 2; ii++) {
                int i = tid + ii * 256; int r = i >> 4, c4 = (i & 15) << 2;
                rbuf[ii] = *reinterpret_cast<const float4*>(Bt + (size_t)(k0 + 32 + r) * ldb + n0 + c4);
            }
        }

        // ---- compute ----
#pragma unroll
        for (int ks = 0; ks < 4; ks++) {
            const int kk = ks * 8;
            unsigned ah[2][4], al[2][4];
#pragma unroll
            for (int mt = 0; mt < 2; mt++) {
                int rb = wm * 32 + mt * 16 + r8;
                ah[mt][0] = __float_as_uint(Ah[rb * GA_LD + kk + lq]);
                ah[mt][1] = __float_as_uint(Ah[(rb + 8) * GA_LD + kk + lq]);
                ah[mt][2] = __float_as_uint(Ah[rb * GA_LD + kk + 4 + lq]);
                ah[mt][3] = __float_as_uint(Ah[(rb + 8) * GA_LD + kk + 4 + lq]);
                al[mt][0] = __float_as_uint(Al[rb * GA_LD + kk + lq]);
                al[mt][1] = __float_as_uint(Al[(rb + 8) * GA_LD + kk + lq]);
                al[mt][2] = __float_as_uint(Al[rb * GA_LD + kk + 4 + lq]);
                al[mt][3] = __float_as_uint(Al[(rb + 8) * GA_LD + kk + 4 + lq]);
            }
            unsigned bhf[4][2], blf[4][2];
#pragma unroll
            for (int nt = 0; nt < 4; nt++) {
                int nb = wn * 32 + nt * 8 + r8;
                bhf[nt][0] = __float_as_uint(Bh[(kk + lq) * GB_LD + nb]);
                bhf[nt][1] = __float_as_uint(Bh[(kk + 4 + lq) * GB_LD + nb]);
                blf[nt][0] = __float_as_uint(Bl[(kk + lq) * GB_LD + nb]);
                blf[nt][1] = __float_as_uint(Bl[(kk + 4 + lq) * GB_LD + nb]);
            }
#pragma unroll
            for (int mt = 0; mt < 2; mt++)
#pragma unroll
                for (int nt = 0; nt < 4; nt++) {
                    mma8(acc[mt][nt], ah[mt], bhf[nt]);
                    mma8(acc[mt][nt], ah[mt], blf[nt]);
                    mma8(acc[mt][nt], al[mt], bhf[nt]);
                }
        }
        __syncthreads();
    }

    // ---- epilogue ----
#pragma unroll
    for (int mt = 0; mt < 2; mt++) {
        int r = row0 + wm * 32 + mt * 16 + r8;
#pragma unroll
        for (int nt = 0; nt < 4; nt++) {
            int c = wn * 32 + nt * 8 + lq * 2;
            if (MODE == 0) {
                int b = r >> 11, s = r & 2047;
                size_t base  = (((size_t)b * NHEAD + blockIdx.y) * SEQL + s) * DKH;
                size_t base2 = base + (size_t)8 * DKH;
                Cq[base + c]      = acc[mt][nt][0];
                Cq[base + c + 1]  = acc[mt][nt][1];
                Cq[base2 + c]     = acc[mt][nt][2];
                Cq[base2 + c + 1] = acc[mt][nt][3];
            } else {
                size_t base = (size_t)r * EMB + blockIdx.y * 64 + c;
                Cq[base]               = acc[mt][nt][0];
                Cq[base + 1]           = acc[mt][nt][1];
                Cq[base + 8 * EMB]     = acc[mt][nt][2];
                Cq[base + 8 * EMB + 1] = acc[mt][nt][3];
            }
        }
    }
}

// ---------------- flash attention (causal), pre-split K/V SMEM tiles --------
// grid: (SEQL/64, BATCHN*NHEAD); block 128 (4 warps, 16 q-rows each)
#define FLD 68
#define VLD 72
#define F_KH 0
#define F_KL (64*FLD)
#define F_VH (2*64*FLD)
#define F_VL (2*64*FLD + 64*VLD)
#define F_PS (2*64*FLD + 2*64*VLD)
#define FSM_FLOATS (3*64*FLD + 2*64*VLD)
#define FSM_BYTES  (FSM_FLOATS*4)
#define LOG2E 1.4426950408889634f

__global__ void __launch_bounds__(128) flash_kernel(const int* __restrict__ maskp)
{
    extern __shared__ float sm[];
    float* Kh = sm + F_KH;    // [64][FLD]  K hi
    float* Kl = sm + F_KL;    // [64][FLD]  K lo
    float* Vh = sm + F_VH;    // [64][VLD]  V hi (row-major: [kv][d])
    float* Vl = sm + F_VL;    // [64][VLD]  V lo
    float* Ps = sm + F_PS;    // [64][FLD]  P tile (also Q staging)

    const int tid  = threadIdx.x;
    const int lane = tid & 31;
    const int warp = tid >> 5;
    const int r8 = lane >> 2, lq = lane & 3;
    const int qt = blockIdx.x;
    const int bh = blockIdx.y;
    const int b = bh >> 4, h = bh & 15;
    const int q0 = qt * 64;

    const float* Q = g_q + (size_t)bh * SEQL * DKH;
    const float* K = g_k + (size_t)bh * SEQL * DKH;
    const float* V = g_v + (size_t)bh * SEQL * DKH;

    // ---- stage Q tile scaled by 8*log2(e) (base-2 softmax) ----
    const float qscale = 8.f * LOG2E;
#pragma unroll
    for (int ii = 0; ii < 8; ii++) {
        int i = tid + ii * 128;
        int r = i >> 4, c4 = (i & 15) << 2;
        float4 v4 = *reinterpret_cast<const float4*>(Q + (size_t)(q0 + r) * DKH + c4);
        float* d = Ps + r * FLD + c4;
        d[0] = v4.x * qscale; d[1] = v4.y * qscale; d[2] = v4.z * qscale; d[3] = v4.w * qscale;
    }
    __syncthreads();

    const int rl = warp * 16 + r8;   // first of this thread's two q-rows
    unsigned qhi[8][4], qlo[8][4];
#pragma unroll
    for (int ks = 0; ks < 8; ks++) {
        split_tf32(Ps[rl * FLD + ks * 8 + lq],           qhi[ks][0], qlo[ks][0]);
        split_tf32(Ps[(rl + 8) * FLD + ks * 8 + lq],     qhi[ks][1], qlo[ks][1]);
        split_tf32(Ps[rl * FLD + ks * 8 + 4 + lq],       qhi[ks][2], qlo[ks][2]);
        split_tf32(Ps[(rl + 8) * FLD + ks * 8 + 4 + lq], qhi[ks][3], qlo[ks][3]);
    }

    float m[2] = { -1e30f, -1e30f };
    float l[2] = { 0.f, 0.f };
    float o[8][4];
#pragma unroll
    for (int i = 0; i < 8; i++)
#pragma unroll
        for (int j = 0; j < 4; j++) o[i][j] = 0.f;

    const int maskv = maskp[0];
    const int ntiles = maskv ? (qt + 1) : (SEQL / 64);

    for (int t = 0; t < ntiles; t++) {
        const int kv0 = t * 64;
        // ---- cooperative K / V load with tf32 split ----
#pragma unroll
        for (int ii = 0; ii < 8; ii++) {
            int i = tid + ii * 128;
            int r = i >> 4, c4 = (i & 15) << 2;
            float4 k4 = *reinterpret_cast<const float4*>(K + (size_t)(kv0 + r) * DKH + c4);
            float kv[4] = { k4.x, k4.y, k4.z, k4.w };
#pragma unroll
            for (int j = 0; j < 4; j++) {
                unsigned hh, ll; split_tf32(kv[j], hh, ll);
                Kh[r * FLD + c4 + j] = __uint_as_float(hh);
                Kl[r * FLD + c4 + j] = __uint_as_float(ll);
            }
            float4 v4 = *reinterpret_cast<const float4*>(V + (size_t)(kv0 + r) * DKH + c4);
            float vv[4] = { v4.x, v4.y, v4.z, v4.w };
#pragma unroll
            for (int j = 0; j < 4; j++) {
                unsigned hh, ll; split_tf32(vv[j], hh, ll);
                Vh[r * VLD + c4 + j] = __uint_as_float(hh);
                Vl[r * VLD + c4 + j] = __uint_as_float(ll);
            }
        }
        __syncthreads();

        // ---- S = Q K^T (TF32x3; scale folded into Q) ----
        float s[8][4];
#pragma unroll
        for (int i = 0; i < 8; i++)
#pragma unroll
            for (int j = 0; j < 4; j++) s[i][j] = 0.f;

#pragma unroll
        for (int ks = 0; ks < 8; ks++) {
            const int kk = ks * 8;
#pragma unroll
            for (int nt = 0; nt < 8; nt++) {
                int nb = nt * 8 + r8;
                unsigned bhv[2], blv[2];
                bhv[0] = __float_as_uint(Kh[nb * FLD + kk + lq]);
                bhv[1] = __float_as_uint(Kh[nb * FLD + kk + 4 + lq]);
                blv[0] = __float_as_uint(Kl[nb * FLD + kk + lq]);
                blv[1] = __float_as_uint(Kl[nb * FLD + kk + 4 + lq]);
                mma8(s[nt], qhi[ks], bhv);
                mma8(s[nt], qhi[ks], blv);
                mma8(s[nt], qlo[ks], bhv);
            }
        }

        // ---- causal mask on diagonal tile ----
        if (maskv && t == qt) {
            int rg0 = q0 + rl;
#pragma unroll
            for (int nt = 0; nt < 8; nt++) {
                int cg = kv0 + nt * 8 + lq * 2;
                if (cg > rg0)         s[nt][0] = -1e30f;
                if (cg + 1 > rg0)     s[nt][1] = -1e30f;
                if (cg > rg0 + 8)     s[nt][2] = -1e30f;
                if (cg + 1 > rg0 + 8) s[nt][3] = -1e30f;
            }
        }

        // ---- online softmax (base 2) ----
#pragma unroll
        for (int sub = 0; sub < 2; sub++) {
            float tm = -1e30f;
#pragma unroll
            for (int nt = 0; nt < 8; nt++)
                tm = fmaxf(tm, fmaxf(s[nt][2 * sub], s[nt][2 * sub + 1]));
            tm = fmaxf(tm, __shfl_xor_sync(0xffffffffu, tm, 1));
            tm = fmaxf(tm, __shfl_xor_sync(0xffffffffu, tm, 2));
            float mn = fmaxf(m[sub], tm);
            float alpha = exp2f(m[sub] - mn);
            float rs = 0.f;
#pragma unroll
            for (int nt = 0; nt < 8; nt++) {
                float p0 = exp2f(s[nt][2 * sub] - mn);
                float p1 = exp2f(s[nt][2 * sub + 1] - mn);
                s[nt][2 * sub] = p0; s[nt][2 * sub + 1] = p1;
                rs += p0 + p1;
            }
            rs += __shfl_xor_sync(0xffffffffu, rs, 1);
            rs += __shfl_xor_sync(0xffffffffu, rs, 2);
            l[sub] = l[sub] * alpha + rs;
            m[sub] = mn;
#pragma unroll
            for (int dt = 0; dt < 8; dt++) {
                o[dt][2 * sub]     *= alpha;
                o[dt][2 * sub + 1] *= alpha;
            }
        }

        // ---- store P (tf32-rounded) to SMEM for PV MMA ----
#pragma unroll
        for (int nt = 0; nt < 8; nt++) {
            int c = nt * 8 + lq * 2;
            Ps[rl * FLD + c]           = __uint_as_float(f2tf(s[nt][0]));
            Ps[rl * FLD + c + 1]       = __uint_as_float(f2tf(s[nt][1]));
            Ps[(rl + 8) * FLD + c]     = __uint_as_float(f2tf(s[nt][2]));
            Ps[(rl + 8) * FLD + c + 1] = __uint_as_float(f2tf(s[nt][3]));
        }
        __syncthreads();

        // ---- O += P * V (P single tf32, V hi+lo) ----
#pragma unroll
        for (int ks = 0; ks < 8; ks++) {
            int kkk = ks * 8 + lq;
            unsigned pa[4];
            pa[0] = __float_as_uint(Ps[rl * FLD + kkk]);
            pa[1] = __float_as_uint(Ps[(rl + 8) * FLD + kkk]);
            pa[2] = __float_as_uint(Ps[rl * FLD + kkk + 4]);
            pa[3] = __float_as_uint(Ps[(rl + 8) * FLD + kkk + 4]);
#pragma unroll
            for (int dt = 0; dt < 8; dt++) {
                int db = dt * 8 + r8;
                unsigned bhv[2], blv[2];
                bhv[0] = __float_as_uint(Vh[(ks * 8 + lq) * VLD + db]);
                bhv[1] = __float_as_uint(Vh[(ks * 8 + 4 + lq) * VLD + db]);
                blv[0] = __float_as_uint(Vl[(ks * 8 + lq) * VLD + db]);
                blv[1] = __float_as_uint(Vl[(ks * 8 + 4 + lq) * VLD + db]);
                mma8(o[dt], pa, bhv);
                mma8(o[dt], pa, blv);
            }
        }
        __syncthreads();
    }

    // ---- epilogue: attn[b, q, h, d] = O / l ----
    float i0 = 1.f / l[0];
    float i1 = 1.f / l[1];
    int rg = q0 + rl;
    size_t ob  = (((size_t)b * SEQL + rg) * NHEAD + h) * DKH;
    size_t ob2 = (((size_t)b * SEQL + rg + 8) * NHEAD + h) * DKH;
#pragma unroll
    for (int dt = 0; dt < 8; dt++) {
        int c = dt * 8 + lq * 2;
        g_attn[ob + c]      = o[dt][0] * i0;
        g_attn[ob + c + 1]  = o[dt][1] * i0;
        g_attn[ob2 + c]     = o[dt][2] * i1;
        g_attn[ob2 + c + 1] = o[dt][3] * i1;
    }
}

// ---------------- launcher ---------------------------------------------------
extern "C" void kernel_launch(void* const* d_in, const int* in_sizes, int n_in,
                              void* d_out, int out_size)
{
    const float* x_q = (const float*)d_in[0];
    const float* x_k = (const float*)d_in[1];
    const float* x_v = (const float*)d_in[2];
    const float* w_q = (const float*)d_in[3];
    const float* w_k = (const float*)d_in[4];
    const float* w_v = (const float*)d_in[5];
    const float* w_o = (const float*)d_in[6];
    const int*   msk = (const int*)d_in[7];
    float* out = (float*)d_out;

    cudaFuncSetAttribute(gemm_x3_kernel<0>, cudaFuncAttributeMaxDynamicSharedMemorySize, GSM_BYTES);
    cudaFuncSetAttribute(gemm_x3_kernel<1>, cudaFuncAttributeMaxDynamicSharedMemorySize, GSM_BYTES);
    cudaFuncSetAttribute(flash_kernel, cudaFuncAttributeMaxDynamicSharedMemorySize, FSM_BYTES);

    gemm_x3_kernel<0><<<dim3(MROWS / 128, NHEAD, 3), 256, GSM_BYTES>>>(
        x_q, x_k, x_v, w_q, w_k, w_v, nullptr);

    flash_kernel<<<dim3(SEQL / 64, BATCHN * NHEAD), 128, FSM_BYTES>>>(msk);

    gemm_x3_kernel<1><<<dim3(MROWS / 128, EMB / 64, 1), 256, GSM_BYTES>>>(
        nullptr, nullptr, nullptr, w_o, nullptr, nullptr, out);
}